// round 12
// baseline (speedup 1.0000x reference)
#include <cuda_runtime.h>
#include <cuda_fp16.h>
#include <mma.h>

#define BB 256
#define TT 512

typedef unsigned long long ull;
using namespace nvcuda;

// ---------------- helpers ----------------
__device__ __forceinline__ float sigf(float x) {
    float t;
    asm("tanh.approx.f32 %0, %1;" : "=f"(t) : "f"(0.5f * x));
    return fmaf(t, 0.5f, 0.5f);
}
__device__ __forceinline__ void quad_select(
    int g, float zm, float p1, float rv, float p2,
    float& zi, float& zf, float& zg, float& zo)
{
    bool lo = (g & 1) != 0;
    bool hi = (g & 2) != 0;
    zi = hi ? (lo ? p2 : rv) : (lo ? p1 : zm);
    zf = hi ? (lo ? rv : p2) : (lo ? zm : p1);
    zg = hi ? (lo ? p1 : zm) : (lo ? p2 : rv);
    zo = hi ? (lo ? zm : p1) : (lo ? rv : p2);
}

// ---------------- device scratch ----------------
__device__ float g_zx1[TT * BB * 512];
__device__ float g_h1 [TT * BB * 128];
__device__ float g_zx2[TT * BB * 256];
__device__ float g_h3 [BB * 64];

// ---------------------------------------------------------------------------
// Tensor-core projection GEMM via wmma (unchanged — verified R9-R11).
// ---------------------------------------------------------------------------
template<int K, int N, bool GATHER>
__global__ __launch_bounds__(256) void proj_gemm_tc(
    const float* __restrict__ A, const float* __restrict__ W,
    float* __restrict__ C)
{
    const int BM = 128;
    const int BK = 32;
    const int ALD = 48;
    const int WLD = 144;

    __shared__ __align__(32) __half As_hi[128 * 48];
    __shared__ __align__(32) __half As_lo[128 * 48];
    __shared__ __align__(32) __half Ws_hi[32 * 144];
    __shared__ __align__(32) __half Ws_lo[32 * 144];

    const int tid  = threadIdx.x;
    const int warp = tid >> 5;
    const int wm   = (warp & 1) * 64;
    const int wn   = (warp >> 1) * 32;
    const int m0   = blockIdx.x * BM;
    const int n0   = blockIdx.y * 128;

    const int arow = tid >> 1;
    const int acol = (tid & 1) * 16;
    const float* a_src;
    {
        int mrow = m0 + arow;
        if (GATHER) {
            int b = mrow & (BB - 1);
            int t = mrow >> 8;
            a_src = A + ((long)b * TT + t) * K;
        } else {
            a_src = A + (long)mrow * K;
        }
    }
    const int wrow = tid >> 3;
    const int wcol = (tid & 7) * 16;

    wmma::fragment<wmma::accumulator, 16, 16, 16, float> acc[4][2];
#pragma unroll
    for (int mi = 0; mi < 4; mi++) {
#pragma unroll
        for (int ni = 0; ni < 2; ni++) {
            wmma::fill_fragment(acc[mi][ni], 0.0f);
        }
    }

    for (int kt = 0; kt < K; kt += BK) {
#pragma unroll
        for (int i4 = 0; i4 < 4; i4++) {
            float4 v = *reinterpret_cast<const float4*>(a_src + kt + acol + i4 * 4);
            float vv[4];
            vv[0] = v.x; vv[1] = v.y; vv[2] = v.z; vv[3] = v.w;
#pragma unroll
            for (int e = 0; e < 4; e++) {
                __half h = __float2half_rn(vv[e]);
                __half l = __float2half_rn(vv[e] - __half2float(h));
                As_hi[arow * ALD + acol + i4 * 4 + e] = h;
                As_lo[arow * ALD + acol + i4 * 4 + e] = l;
            }
        }
#pragma unroll
        for (int i4 = 0; i4 < 4; i4++) {
            float4 v = *reinterpret_cast<const float4*>(
                W + (long)(kt + wrow) * N + n0 + wcol + i4 * 4);
            float vv[4];
            vv[0] = v.x; vv[1] = v.y; vv[2] = v.z; vv[3] = v.w;
#pragma unroll
            for (int e = 0; e < 4; e++) {
                __half h = __float2half_rn(vv[e]);
                __half l = __float2half_rn(vv[e] - __half2float(h));
                Ws_hi[wrow * WLD + wcol + i4 * 4 + e] = h;
                Ws_lo[wrow * WLD + wcol + i4 * 4 + e] = l;
            }
        }
        __syncthreads();

#pragma unroll
        for (int k16 = 0; k16 < BK / 16; k16++) {
            const int k0 = k16 * 16;
            wmma::fragment<wmma::matrix_a, 16, 16, 16, __half, wmma::row_major> ah[4];
            wmma::fragment<wmma::matrix_a, 16, 16, 16, __half, wmma::row_major> al[4];
            wmma::fragment<wmma::matrix_b, 16, 16, 16, __half, wmma::row_major> bh[2];
            wmma::fragment<wmma::matrix_b, 16, 16, 16, __half, wmma::row_major> bl[2];
#pragma unroll
            for (int mi = 0; mi < 4; mi++) {
                wmma::load_matrix_sync(ah[mi], &As_hi[(wm + mi * 16) * ALD + k0], ALD);
                wmma::load_matrix_sync(al[mi], &As_lo[(wm + mi * 16) * ALD + k0], ALD);
            }
#pragma unroll
            for (int ni = 0; ni < 2; ni++) {
                wmma::load_matrix_sync(bh[ni], &Ws_hi[k0 * WLD + wn + ni * 16], WLD);
                wmma::load_matrix_sync(bl[ni], &Ws_lo[k0 * WLD + wn + ni * 16], WLD);
            }
#pragma unroll
            for (int mi = 0; mi < 4; mi++) {
#pragma unroll
                for (int ni = 0; ni < 2; ni++) {
                    wmma::mma_sync(acc[mi][ni], ah[mi], bh[ni], acc[mi][ni]);
                    wmma::mma_sync(acc[mi][ni], al[mi], bh[ni], acc[mi][ni]);
                    wmma::mma_sync(acc[mi][ni], ah[mi], bl[ni], acc[mi][ni]);
                }
            }
        }
        __syncthreads();
    }

#pragma unroll
    for (int mi = 0; mi < 4; mi++) {
#pragma unroll
        for (int ni = 0; ni < 2; ni++) {
            float* dst = C + (long)(m0 + wm + mi * 16) * N + n0 + wn + ni * 16;
            wmma::store_matrix_sync(dst, acc[mi][ni], N, wmma::mem_row_major);
        }
    }
}

// ---------------------------------------------------------------------------
// Fused layers 2+3: lstm2 step -> proj3 matvec -> lstm3 step, per batch row.
// 256 CTAs x 128 threads (2 CTAs/SM). Thread: g = tid&3, j = tid>>2 (0..31);
// owns gate cols cA = g*64+j and cB = g*64+j+32 for BOTH layers.
// Uw2, Uw3 as fp16 k-pair registers; W3 transposed in smem [c][72] halves
// (144B row stride -> conflict-free LDS.128). h2/h3 states fp16 in smem.
// Only input: zx2 [T,B,256]. Only output: last-step h3 [B,64].
// ---------------------------------------------------------------------------
__global__ __launch_bounds__(128) void lstm23_rec(
    const float* __restrict__ zx,     // [T,B,256] layer-2 input projection
    const float* __restrict__ Uw2,    // [64,256]
    const float* __restrict__ b2,     // [256]
    const float* __restrict__ W3,     // [64,256]
    const float* __restrict__ b3,     // [256]
    const float* __restrict__ Uw3,    // [64,256]
    float* __restrict__ h3_out)       // [B,64]
{
    const int U = 64;
    const int G = 256;
    const int PF = 4;
    const long ZSTRIDE = (long)BB * G;

    __shared__ __align__(16) __half h2_s[2][64];
    __shared__ __align__(16) __half h3_s[2][64];
    __shared__ __align__(16) __half W3t[256 * 72];   // [c][k], 72-half rows

    const int tid = threadIdx.x;
    const int row = blockIdx.x;
    const int g   = tid & 3;
    const int j   = tid >> 2;            // 0..31
    const int cA  = g * U + j;
    const int cB  = g * U + j + 32;
    const int unit = j + ((g & 2) << 4); // j or j+32
    const bool useB = (g & 2) != 0;

    // weights: Uw2, Uw3 k-pairs in registers
    half2 wA[32], wB[32], uA[32], uB[32];
#pragma unroll
    for (int k2 = 0; k2 < 32; k2++) {
        wA[k2] = __floats2half2_rn(Uw2[(2 * k2) * G + cA], Uw2[(2 * k2 + 1) * G + cA]);
        wB[k2] = __floats2half2_rn(Uw2[(2 * k2) * G + cB], Uw2[(2 * k2 + 1) * G + cB]);
        uA[k2] = __floats2half2_rn(Uw3[(2 * k2) * G + cA], Uw3[(2 * k2 + 1) * G + cA]);
        uB[k2] = __floats2half2_rn(Uw3[(2 * k2) * G + cB], Uw3[(2 * k2 + 1) * G + cB]);
    }
    // W3 transposed into smem: W3t[c][k] = W3[k][c]
    for (int i = tid; i < 256 * 64; i += 128) {
        int c = i >> 6;
        int k = i & 63;
        W3t[c * 72 + k] = __float2half_rn(W3[k * G + c]);
    }
    if (tid < 64) {
        h2_s[0][tid] = __float2half_rn(0.f);
        h2_s[1][tid] = __float2half_rn(0.f);
        h3_s[0][tid] = __float2half_rn(0.f);
        h3_s[1][tid] = __float2half_rn(0.f);
    }
    const float bzA = b2[cA];
    const float bzB = b2[cB];
    const float b3A = b3[cA];
    const float b3B = b3[cB];
    __syncthreads();

    const float* zpA = zx + (long)row * G + cA;
    const float* zpB = zx + (long)row * G + cB;

    float creg2 = 0.f;
    float creg3 = 0.f;
    float zAr[4];
    float zBr[4];
#pragma unroll
    for (int p = 0; p < PF; p++) {
        zAr[p] = zpA[(long)p * ZSTRIDE];
        zBr[p] = zpB[(long)p * ZSTRIDE];
    }

    int cur = 0;
#pragma unroll 2
    for (int t = 0; t < TT; t++) {
        const int s = t & (PF - 1);
        float zA = zAr[s] + bzA;
        float zB = zBr[s] + bzB;
        if (t + PF < TT) {
            zAr[s] = zpA[(long)(t + PF) * ZSTRIDE];
            zBr[s] = zpB[(long)(t + PF) * ZSTRIDE];
        }

        // ---- lstm2 recurrent matvec (h2[t-1]) ----
        {
            uint4 hbuf[8];
            const uint4* hsp = reinterpret_cast<const uint4*>(&h2_s[cur][0]);
#pragma unroll
            for (int i = 0; i < 8; i++) {
                hbuf[i] = hsp[i];
            }
            const half2* hp = reinterpret_cast<const half2*>(hbuf);
#pragma unroll
            for (int grp = 0; grp < 4; grp++) {
                half2 sA = __floats2half2_rn(0.f, 0.f);
                half2 sB = __floats2half2_rn(0.f, 0.f);
#pragma unroll
                for (int q = 0; q < 8; q++) {
                    const int k2 = grp * 8 + q;
                    sA = __hfma2(wA[k2], hp[k2], sA);
                    sB = __hfma2(wB[k2], hp[k2], sB);
                }
                float2 fA = __half22float2(sA);
                float2 fB = __half22float2(sB);
                zA += fA.x + fA.y;
                zB += fB.x + fB.y;
            }
        }

        // ---- lstm2 gate combine ----
        {
            float sA1 = __shfl_xor_sync(0xffffffffu, zA, 1);
            float sA2 = __shfl_xor_sync(0xffffffffu, zA, 2);
            float sA3 = __shfl_xor_sync(0xffffffffu, zA, 3);
            float sB1 = __shfl_xor_sync(0xffffffffu, zB, 1);
            float sB2 = __shfl_xor_sync(0xffffffffu, zB, 2);
            float sB3 = __shfl_xor_sync(0xffffffffu, zB, 3);

            float mine = useB ? zB  : zA;
            float p1   = useB ? sB1 : sA1;
            float rv   = useB ? sB2 : sA2;
            float p2   = useB ? sB3 : sA3;

            float zi, zf, zg_, zoo;
            quad_select(g, mine, p1, rv, p2, zi, zf, zg_, zoo);

            float ig = sigf(zi);
            float fg = sigf(zf);
            float gg = fmaxf(zg_, 0.f);
            float og = sigf(zoo);
            creg2 = fg * creg2 + ig * gg;
            float h2v = og * fmaxf(creg2, 0.f);

            if ((g & 1) == 0) {
                h2_s[cur ^ 1][unit] = __float2half_rn(h2v);
            }
        }
        __syncthreads();   // barrier 1: h2[t] published

        // ---- proj3: z3 = h2[t] @ W3 + b3 (per-thread 2 gate cols) ----
        float z3A = b3A;
        float z3B = b3B;
        {
            uint4 h2buf[8];
            const uint4* h2sp = reinterpret_cast<const uint4*>(&h2_s[cur ^ 1][0]);
#pragma unroll
            for (int i = 0; i < 8; i++) {
                h2buf[i] = h2sp[i];
            }
            const half2* h2p = reinterpret_cast<const half2*>(h2buf);

            uint4 w3Ab[8];
            uint4 w3Bb[8];
            const uint4* wap = reinterpret_cast<const uint4*>(&W3t[cA * 72]);
            const uint4* wbp = reinterpret_cast<const uint4*>(&W3t[cB * 72]);
#pragma unroll
            for (int i = 0; i < 8; i++) {
                w3Ab[i] = wap[i];
                w3Bb[i] = wbp[i];
            }
            const half2* wa = reinterpret_cast<const half2*>(w3Ab);
            const half2* wb = reinterpret_cast<const half2*>(w3Bb);
#pragma unroll
            for (int grp = 0; grp < 4; grp++) {
                half2 sA = __floats2half2_rn(0.f, 0.f);
                half2 sB = __floats2half2_rn(0.f, 0.f);
#pragma unroll
                for (int q = 0; q < 8; q++) {
                    const int k2 = grp * 8 + q;
                    sA = __hfma2(wa[k2], h2p[k2], sA);
                    sB = __hfma2(wb[k2], h2p[k2], sB);
                }
                float2 fA = __half22float2(sA);
                float2 fB = __half22float2(sB);
                z3A += fA.x + fA.y;
                z3B += fB.x + fB.y;
            }
        }

        // ---- lstm3 recurrent matvec (h3[t-1]) ----
        {
            uint4 hbuf[8];
            const uint4* hsp = reinterpret_cast<const uint4*>(&h3_s[cur][0]);
#pragma unroll
            for (int i = 0; i < 8; i++) {
                hbuf[i] = hsp[i];
            }
            const half2* hp = reinterpret_cast<const half2*>(hbuf);
#pragma unroll
            for (int grp = 0; grp < 4; grp++) {
                half2 sA = __floats2half2_rn(0.f, 0.f);
                half2 sB = __floats2half2_rn(0.f, 0.f);
#pragma unroll
                for (int q = 0; q < 8; q++) {
                    const int k2 = grp * 8 + q;
                    sA = __hfma2(uA[k2], hp[k2], sA);
                    sB = __hfma2(uB[k2], hp[k2], sB);
                }
                float2 fA = __half22float2(sA);
                float2 fB = __half22float2(sB);
                z3A += fA.x + fA.y;
                z3B += fB.x + fB.y;
            }
        }

        // ---- lstm3 gate combine ----
        {
            float sA1 = __shfl_xor_sync(0xffffffffu, z3A, 1);
            float sA2 = __shfl_xor_sync(0xffffffffu, z3A, 2);
            float sA3 = __shfl_xor_sync(0xffffffffu, z3A, 3);
            float sB1 = __shfl_xor_sync(0xffffffffu, z3B, 1);
            float sB2 = __shfl_xor_sync(0xffffffffu, z3B, 2);
            float sB3 = __shfl_xor_sync(0xffffffffu, z3B, 3);

            float mine = useB ? z3B : z3A;
            float p1   = useB ? sB1 : sA1;
            float rv   = useB ? sB2 : sA2;
            float p2   = useB ? sB3 : sA3;

            float zi, zf, zg_, zoo;
            quad_select(g, mine, p1, rv, p2, zi, zf, zg_, zoo);

            float ig = sigf(zi);
            float fg = sigf(zf);
            float gg = fmaxf(zg_, 0.f);
            float og = sigf(zoo);
            creg3 = fg * creg3 + ig * gg;
            float h3v = og * fmaxf(creg3, 0.f);

            if ((g & 1) == 0) {
                h3_s[cur ^ 1][unit] = __float2half_rn(h3v);
                if (t == TT - 1) {
                    h3_out[(long)row * U + unit] = h3v;
                }
            }
        }
        __syncthreads();   // barrier 2: h3[t] + next-step h2 state ready
        cur ^= 1;
    }
}

// ---------------------------------------------------------------------------
// Layer-1 recurrence (unchanged — verified R9-R11).
// ---------------------------------------------------------------------------
__global__ __launch_bounds__(256) void lstm1_rec(
    const float* __restrict__ zx,
    const float* __restrict__ Uw,
    const float* __restrict__ bias,
    float* __restrict__ h_out)
{
    const int U = 128;
    const int G = 512;
    const int PF = 4;
    const long ZSTRIDE = (long)BB * G;
    __shared__ __half h_s[2][2][128];

    const int tid = threadIdx.x;
    const int b0  = blockIdx.x * 2;
    const int g   = tid & 3;
    const int j0  = tid >> 2;
    const int c0  = g * U + j0;
    const int c1  = g * U + j0 + 64;
    const int myrow = (g >> 1) & 1;

    half2 w0[64];
    half2 w1[64];
#pragma unroll
    for (int k2 = 0; k2 < 64; k2++) {
        w0[k2] = __floats2half2_rn(Uw[(2 * k2) * G + c0], Uw[(2 * k2 + 1) * G + c0]);
        w1[k2] = __floats2half2_rn(Uw[(2 * k2) * G + c1], Uw[(2 * k2 + 1) * G + c1]);
    }
    for (int i = tid; i < 512; i += 256) {
        (&h_s[0][0][0])[i] = __float2half_rn(0.f);
    }
    const float bz0 = bias[c0];
    const float bz1 = bias[c1];
    __syncthreads();

    const float* z00p = zx + (long)b0 * G + c0;
    const float* z01p = z00p + G;
    const float* z10p = zx + (long)b0 * G + c1;
    const float* z11p = z10p + G;

    float c_a = 0.f;
    float c_b = 0.f;
    float zA0[4];
    float zA1[4];
    float zB0[4];
    float zB1[4];
#pragma unroll
    for (int p = 0; p < PF; p++) {
        zA0[p] = z00p[(long)p * ZSTRIDE];
        zA1[p] = z01p[(long)p * ZSTRIDE];
        zB0[p] = z10p[(long)p * ZSTRIDE];
        zB1[p] = z11p[(long)p * ZSTRIDE];
    }

    int cur = 0;
#pragma unroll 4
    for (int t = 0; t < TT; t++) {
        const int s = t & (PF - 1);
        float a00 = zA0[s] + bz0;
        float a01 = zA1[s] + bz0;
        float a10 = zB0[s] + bz1;
        float a11 = zB1[s] + bz1;
        if (t + PF < TT) {
            zA0[s] = z00p[(long)(t + PF) * ZSTRIDE];
            zA1[s] = z01p[(long)(t + PF) * ZSTRIDE];
            zB0[s] = z10p[(long)(t + PF) * ZSTRIDE];
            zB1[s] = z11p[(long)(t + PF) * ZSTRIDE];
        }

#pragma unroll
        for (int kb = 0; kb < 4; kb++) {
            half2 s00 = __floats2half2_rn(0.f, 0.f);
            half2 s01 = __floats2half2_rn(0.f, 0.f);
            half2 s10 = __floats2half2_rn(0.f, 0.f);
            half2 s11 = __floats2half2_rn(0.f, 0.f);
#pragma unroll
            for (int k8 = 0; k8 < 4; k8++) {
                const int kbase = kb * 32 + k8 * 8;
                uint4 hv0 = *reinterpret_cast<const uint4*>(&h_s[cur][0][kbase]);
                uint4 hv1 = *reinterpret_cast<const uint4*>(&h_s[cur][1][kbase]);
                const half2* hp0 = reinterpret_cast<const half2*>(&hv0);
                const half2* hp1 = reinterpret_cast<const half2*>(&hv1);
#pragma unroll
                for (int q = 0; q < 4; q++) {
                    const int k2 = kbase / 2 + q;
                    s00 = __hfma2(w0[k2], hp0[q], s00);
                    s01 = __hfma2(w0[k2], hp1[q], s01);
                    s10 = __hfma2(w1[k2], hp0[q], s10);
                    s11 = __hfma2(w1[k2], hp1[q], s11);
                }
            }
            float2 fa = __half22float2(s00);
            float2 fb = __half22float2(s01);
            float2 fc = __half22float2(s10);
            float2 fd = __half22float2(s11);
            a00 += fa.x + fa.y;
            a01 += fb.x + fb.y;
            a10 += fc.x + fc.y;
            a11 += fd.x + fd.y;
        }

        float mineA  = myrow ? a01 : a00;
        float otherA = myrow ? a00 : a01;
        float mineB  = myrow ? a11 : a10;
        float otherB = myrow ? a10 : a11;
        float p1A = __shfl_xor_sync(0xffffffffu, mineA,  1);
        float rvA = __shfl_xor_sync(0xffffffffu, otherA, 2);
        float p2A = __shfl_xor_sync(0xffffffffu, otherA, 3);
        float p1B = __shfl_xor_sync(0xffffffffu, mineB,  1);
        float rvB = __shfl_xor_sync(0xffffffffu, otherB, 2);
        float p2B = __shfl_xor_sync(0xffffffffu, otherB, 3);

        float zi, zf, zg_, zoo;
        quad_select(g, mineA, p1A, rvA, p2A, zi, zf, zg_, zoo);
        float ig = sigf(zi);
        float fg = sigf(zf);
        float og = sigf(zoo);
        c_a = fg * c_a + ig * fmaxf(zg_, 0.f);
        float hA = og * fmaxf(c_a, 0.f);

        quad_select(g, mineB, p1B, rvB, p2B, zi, zf, zg_, zoo);
        ig = sigf(zi);
        fg = sigf(zf);
        og = sigf(zoo);
        c_b = fg * c_b + ig * fmaxf(zg_, 0.f);
        float hB = og * fmaxf(c_b, 0.f);

        if ((g & 1) == 0) {
            h_s[cur ^ 1][myrow][j0]      = __float2half_rn(hA);
            h_s[cur ^ 1][myrow][j0 + 64] = __float2half_rn(hB);
            float* ho = h_out + ((long)t * BB + b0 + myrow) * U;
            ho[j0]      = hA;
            ho[j0 + 64] = hB;
        }
        __syncthreads();
        cur ^= 1;
    }
}

// ---------------- dense head ----------------
__global__ __launch_bounds__(256) void dense_kernel(
    const float* __restrict__ h3, const float* __restrict__ Wd1,
    const float* __restrict__ bd1, const float* __restrict__ Wd2,
    const float* __restrict__ bd2, float* __restrict__ out)
{
    __shared__ float w1[64 * 32];
    __shared__ float w2[32];
    __shared__ float b1s[32];
    const int tid = threadIdx.x;
    for (int i = tid; i < 64 * 32; i += 256) {
        w1[i] = Wd1[i];
    }
    if (tid < 32) {
        w2[tid] = Wd2[tid];
        b1s[tid] = bd1[tid];
    }
    __syncthreads();

    float hr[64];
#pragma unroll
    for (int k4 = 0; k4 < 16; k4++) {
        *reinterpret_cast<float4*>(&hr[4 * k4]) =
            *reinterpret_cast<const float4*>(&h3[tid * 64 + 4 * k4]);
    }

    float o = bd2[0];
#pragma unroll 4
    for (int jj = 0; jj < 32; jj++) {
        float d = b1s[jj];
#pragma unroll
        for (int k = 0; k < 64; k++) {
            d += hr[k] * w1[k * 32 + jj];
        }
        o += fmaxf(d, 0.f) * w2[jj];
    }
    out[tid] = o;
}

// ---------------- launcher ----------------
extern "C" void kernel_launch(void* const* d_in, const int* in_sizes, int n_in,
                              void* d_out, int out_size)
{
    const float* x   = (const float*)d_in[0];
    const float* W1  = (const float*)d_in[1];
    const float* Uw1 = (const float*)d_in[2];
    const float* b1  = (const float*)d_in[3];
    const float* W2  = (const float*)d_in[4];
    const float* Uw2 = (const float*)d_in[5];
    const float* b2  = (const float*)d_in[6];
    const float* W3  = (const float*)d_in[7];
    const float* Uw3 = (const float*)d_in[8];
    const float* b3  = (const float*)d_in[9];
    const float* Wd1 = (const float*)d_in[10];
    const float* bd1 = (const float*)d_in[11];
    const float* Wd2 = (const float*)d_in[12];
    const float* bd2 = (const float*)d_in[13];

    float* zx1;
    float* h1;
    float* zx2;
    float* h3;
    cudaGetSymbolAddress((void**)&zx1, g_zx1);
    cudaGetSymbolAddress((void**)&h1,  g_h1);
    cudaGetSymbolAddress((void**)&zx2, g_zx2);
    cudaGetSymbolAddress((void**)&h3,  g_h3);

    proj_gemm_tc<64, 512, true ><<<dim3(1024, 4), 256>>>(x,  W1, zx1);
    lstm1_rec<<<128, 256>>>(zx1, Uw1, b1, h1);

    proj_gemm_tc<128, 256, false><<<dim3(1024, 2), 256>>>(h1, W2, zx2);
    lstm23_rec<<<256, 128>>>(zx2, Uw2, b2, W3, b3, Uw3, h3);

    dense_kernel<<<1, 256>>>(h3, Wd1, bd1, Wd2, bd2, (float*)d_out);
}

// round 13
// speedup vs baseline: 1.4048x; 1.4048x over previous
#include <cuda_runtime.h>
#include <cuda_fp16.h>
#include <mma.h>

#define BB 256
#define TT 512

using namespace nvcuda;

// ---------------- helpers ----------------
__device__ __forceinline__ float sigf(float x) {
    float t;
    asm("tanh.approx.f32 %0, %1;" : "=f"(t) : "f"(0.5f * x));
    return fmaf(t, 0.5f, 0.5f);
}
__device__ __forceinline__ void quad_select(
    int g, float zm, float p1, float rv, float p2,
    float& zi, float& zf, float& zg, float& zo)
{
    bool lo = (g & 1) != 0;
    bool hi = (g & 2) != 0;
    zi = hi ? (lo ? p2 : rv) : (lo ? p1 : zm);
    zf = hi ? (lo ? rv : p2) : (lo ? zm : p1);
    zg = hi ? (lo ? p1 : zm) : (lo ? p2 : rv);
    zo = hi ? (lo ? zm : p1) : (lo ? rv : p2);
}

// ---------------- device scratch ----------------
__device__ float  g_zx1[TT * BB * 512];
__device__ float  g_zx2[TT * BB * 256];
__device__ float  g_zx3[TT * BB * 256];
__device__ float  g_h3 [BB * 64];
__device__ __half g_xhi[BB * TT * 64];
__device__ __half g_xlo[BB * TT * 64];
__device__ __half g_h1hi[TT * BB * 128];
__device__ __half g_h1lo[TT * BB * 128];
__device__ __half g_h2hi[TT * BB * 64];
__device__ __half g_h2lo[TT * BB * 64];
__device__ __half g_w1hi[64 * 512];
__device__ __half g_w1lo[64 * 512];
__device__ __half g_w2hi[128 * 256];
__device__ __half g_w2lo[128 * 256];
__device__ __half g_w3hi[64 * 256];
__device__ __half g_w3lo[64 * 256];

// ---------------------------------------------------------------------------
// fp32 -> (hi, lo) fp16 split, grid-stride.
// ---------------------------------------------------------------------------
__global__ __launch_bounds__(256) void split_kernel(
    const float* __restrict__ src, __half* __restrict__ hi,
    __half* __restrict__ lo, int n)
{
    for (int i = blockIdx.x * 256 + threadIdx.x; i < n; i += gridDim.x * 256) {
        float v = src[i];
        __half h = __float2half_rn(v);
        hi[i] = h;
        lo[i] = __float2half_rn(v - __half2float(h));
    }
}

// ---------------------------------------------------------------------------
// TC projection GEMM reading PRE-SPLIT fp16 inputs (smem stage = pure copies).
// C[m][n] = A_row(m).W[:,n]; acc = Ahi*Whi + Alo*Whi + Ahi*Wlo (fp32).
// CTA tile 128x128, BK=32, 8 warps (2M x 4N), warp tile 64x32.
// ---------------------------------------------------------------------------
template<int K, int N, bool GATHER>
__global__ __launch_bounds__(256) void proj_gemm_tc(
    const __half* __restrict__ Ahi, const __half* __restrict__ Alo,
    const __half* __restrict__ Whi, const __half* __restrict__ Wlo,
    float* __restrict__ C)
{
    const int BM = 128;
    const int BK = 32;
    const int ALD = 48;
    const int WLD = 144;

    __shared__ __align__(32) __half As_hi[128 * 48];
    __shared__ __align__(32) __half As_lo[128 * 48];
    __shared__ __align__(32) __half Ws_hi[32 * 144];
    __shared__ __align__(32) __half Ws_lo[32 * 144];

    const int tid  = threadIdx.x;
    const int warp = tid >> 5;
    const int wm   = (warp & 1) * 64;
    const int wn   = (warp >> 1) * 32;
    const int m0   = blockIdx.x * BM;
    const int n0   = blockIdx.y * 128;

    const int arow = tid >> 1;
    const int acol = (tid & 1) * 16;
    long a_off;
    {
        int mrow = m0 + arow;
        if (GATHER) {
            int b = mrow & (BB - 1);
            int t = mrow >> 8;
            a_off = ((long)b * TT + t) * K;
        } else {
            a_off = (long)mrow * K;
        }
    }
    const int wrow = tid >> 3;
    const int wcol = (tid & 7) * 16;

    wmma::fragment<wmma::accumulator, 16, 16, 16, float> acc[4][2];
#pragma unroll
    for (int mi = 0; mi < 4; mi++) {
#pragma unroll
        for (int ni = 0; ni < 2; ni++) {
            wmma::fill_fragment(acc[mi][ni], 0.0f);
        }
    }

    for (int kt = 0; kt < K; kt += BK) {
        // A tile: pure copy, 16 halves hi + 16 lo per thread
        {
            const uint4* sh = reinterpret_cast<const uint4*>(Ahi + a_off + kt + acol);
            const uint4* sl = reinterpret_cast<const uint4*>(Alo + a_off + kt + acol);
            uint4* dh = reinterpret_cast<uint4*>(&As_hi[arow * ALD + acol]);
            uint4* dl = reinterpret_cast<uint4*>(&As_lo[arow * ALD + acol]);
            dh[0] = sh[0];
            dh[1] = sh[1];
            dl[0] = sl[0];
            dl[1] = sl[1];
        }
        // W tile: pure copy
        {
            long w_off = (long)(kt + wrow) * N + n0 + wcol;
            const uint4* sh = reinterpret_cast<const uint4*>(Whi + w_off);
            const uint4* sl = reinterpret_cast<const uint4*>(Wlo + w_off);
            uint4* dh = reinterpret_cast<uint4*>(&Ws_hi[wrow * WLD + wcol]);
            uint4* dl = reinterpret_cast<uint4*>(&Ws_lo[wrow * WLD + wcol]);
            dh[0] = sh[0];
            dh[1] = sh[1];
            dl[0] = sl[0];
            dl[1] = sl[1];
        }
        __syncthreads();

#pragma unroll
        for (int k16 = 0; k16 < BK / 16; k16++) {
            const int k0 = k16 * 16;
            wmma::fragment<wmma::matrix_a, 16, 16, 16, __half, wmma::row_major> ah[4];
            wmma::fragment<wmma::matrix_a, 16, 16, 16, __half, wmma::row_major> al[4];
            wmma::fragment<wmma::matrix_b, 16, 16, 16, __half, wmma::row_major> bh[2];
            wmma::fragment<wmma::matrix_b, 16, 16, 16, __half, wmma::row_major> bl[2];
#pragma unroll
            for (int mi = 0; mi < 4; mi++) {
                wmma::load_matrix_sync(ah[mi], &As_hi[(wm + mi * 16) * ALD + k0], ALD);
                wmma::load_matrix_sync(al[mi], &As_lo[(wm + mi * 16) * ALD + k0], ALD);
            }
#pragma unroll
            for (int ni = 0; ni < 2; ni++) {
                wmma::load_matrix_sync(bh[ni], &Ws_hi[k0 * WLD + wn + ni * 16], WLD);
                wmma::load_matrix_sync(bl[ni], &Ws_lo[k0 * WLD + wn + ni * 16], WLD);
            }
#pragma unroll
            for (int mi = 0; mi < 4; mi++) {
#pragma unroll
                for (int ni = 0; ni < 2; ni++) {
                    wmma::mma_sync(acc[mi][ni], ah[mi], bh[ni], acc[mi][ni]);
                    wmma::mma_sync(acc[mi][ni], al[mi], bh[ni], acc[mi][ni]);
                    wmma::mma_sync(acc[mi][ni], ah[mi], bl[ni], acc[mi][ni]);
                }
            }
        }
        __syncthreads();
    }

#pragma unroll
    for (int mi = 0; mi < 4; mi++) {
#pragma unroll
        for (int ni = 0; ni < 2; ni++) {
            float* dst = C + (long)(m0 + wm + mi * 16) * N + n0 + wn + ni * 16;
            wmma::store_matrix_sync(dst, acc[mi][ni], N, wmma::mem_row_major);
        }
    }
}

// ---------------------------------------------------------------------------
// Layer-2/3 recurrence (R11 structure, verified). WRITE_ALL=true writes h as
// hi/lo fp16 pair (for the next projection); false writes last-step fp32.
// ---------------------------------------------------------------------------
template<bool WRITE_ALL>
__global__ __launch_bounds__(128) void lstm64_rec(
    const float* __restrict__ zx,
    const float* __restrict__ Uw,
    const float* __restrict__ bias,
    __half* __restrict__ hhi,
    __half* __restrict__ hlo,
    float* __restrict__ hout_f32)
{
    const int U = 64;
    const int G = 256;
    const int PF = 4;
    const long ZSTRIDE = (long)BB * G;
    __shared__ __align__(16) __half h_s[2][64];

    const int tid = threadIdx.x;
    const int row = blockIdx.x;
    const int g   = tid & 3;
    const int j   = tid >> 2;
    const int cA  = g * U + j;
    const int cB  = g * U + j + 32;
    const int unit = j + ((g & 2) << 4);
    const bool useB = (g & 2) != 0;

    half2 wA[32];
    half2 wB[32];
#pragma unroll
    for (int k2 = 0; k2 < 32; k2++) {
        wA[k2] = __floats2half2_rn(Uw[(2 * k2) * G + cA], Uw[(2 * k2 + 1) * G + cA]);
        wB[k2] = __floats2half2_rn(Uw[(2 * k2) * G + cB], Uw[(2 * k2 + 1) * G + cB]);
    }
    (&h_s[0][0])[tid] = __float2half_rn(0.f);
    const float bzA = bias[cA];
    const float bzB = bias[cB];
    __syncthreads();

    const float* zpA = zx + (long)row * G + cA;
    const float* zpB = zx + (long)row * G + cB;

    float creg = 0.f;
    float zAr[4];
    float zBr[4];
#pragma unroll
    for (int p = 0; p < PF; p++) {
        zAr[p] = zpA[(long)p * ZSTRIDE];
        zBr[p] = zpB[(long)p * ZSTRIDE];
    }

    int cur = 0;
#pragma unroll 4
    for (int t = 0; t < TT; t++) {
        const int s = t & (PF - 1);
        float zA = zAr[s] + bzA;
        float zB = zBr[s] + bzB;
        if (t + PF < TT) {
            zAr[s] = zpA[(long)(t + PF) * ZSTRIDE];
            zBr[s] = zpB[(long)(t + PF) * ZSTRIDE];
        }

        uint4 hbuf[8];
        const uint4* hsp = reinterpret_cast<const uint4*>(&h_s[cur][0]);
#pragma unroll
        for (int i = 0; i < 8; i++) {
            hbuf[i] = hsp[i];
        }
        const half2* hp = reinterpret_cast<const half2*>(hbuf);

#pragma unroll
        for (int grp = 0; grp < 4; grp++) {
            half2 sA = __floats2half2_rn(0.f, 0.f);
            half2 sB = __floats2half2_rn(0.f, 0.f);
#pragma unroll
            for (int q = 0; q < 8; q++) {
                const int k2 = grp * 8 + q;
                sA = __hfma2(wA[k2], hp[k2], sA);
                sB = __hfma2(wB[k2], hp[k2], sB);
            }
            float2 fA = __half22float2(sA);
            float2 fB = __half22float2(sB);
            zA += fA.x + fA.y;
            zB += fB.x + fB.y;
        }

        float sA1 = __shfl_xor_sync(0xffffffffu, zA, 1);
        float sA2 = __shfl_xor_sync(0xffffffffu, zA, 2);
        float sA3 = __shfl_xor_sync(0xffffffffu, zA, 3);
        float sB1 = __shfl_xor_sync(0xffffffffu, zB, 1);
        float sB2 = __shfl_xor_sync(0xffffffffu, zB, 2);
        float sB3 = __shfl_xor_sync(0xffffffffu, zB, 3);

        float mine = useB ? zB  : zA;
        float p1   = useB ? sB1 : sA1;
        float rv   = useB ? sB2 : sA2;
        float p2   = useB ? sB3 : sA3;

        float zi, zf, zg_, zoo;
        quad_select(g, mine, p1, rv, p2, zi, zf, zg_, zoo);

        float ig = sigf(zi);
        float fg = sigf(zf);
        float gg = fmaxf(zg_, 0.f);
        float og = sigf(zoo);
        creg = fg * creg + ig * gg;
        float h = og * fmaxf(creg, 0.f);

        if ((g & 1) == 0) {
            __half hh = __float2half_rn(h);
            h_s[cur ^ 1][unit] = hh;
            if (WRITE_ALL) {
                long o = ((long)t * BB + row) * U + unit;
                hhi[o] = hh;
                hlo[o] = __float2half_rn(h - __half2float(hh));
            } else if (t == TT - 1) {
                hout_f32[(long)row * U + unit] = h;
            }
        }
        __syncthreads();
        cur ^= 1;
    }
}

// ---------------------------------------------------------------------------
// Layer-1 recurrence (R11 structure, verified); h output as hi/lo fp16.
// ---------------------------------------------------------------------------
__global__ __launch_bounds__(256) void lstm1_rec(
    const float* __restrict__ zx,
    const float* __restrict__ Uw,
    const float* __restrict__ bias,
    __half* __restrict__ hhi,
    __half* __restrict__ hlo)
{
    const int U = 128;
    const int G = 512;
    const int PF = 4;
    const long ZSTRIDE = (long)BB * G;
    __shared__ __half h_s[2][2][128];

    const int tid = threadIdx.x;
    const int b0  = blockIdx.x * 2;
    const int g   = tid & 3;
    const int j0  = tid >> 2;
    const int c0  = g * U + j0;
    const int c1  = g * U + j0 + 64;
    const int myrow = (g >> 1) & 1;

    half2 w0[64];
    half2 w1[64];
#pragma unroll
    for (int k2 = 0; k2 < 64; k2++) {
        w0[k2] = __floats2half2_rn(Uw[(2 * k2) * G + c0], Uw[(2 * k2 + 1) * G + c0]);
        w1[k2] = __floats2half2_rn(Uw[(2 * k2) * G + c1], Uw[(2 * k2 + 1) * G + c1]);
    }
    for (int i = tid; i < 512; i += 256) {
        (&h_s[0][0][0])[i] = __float2half_rn(0.f);
    }
    const float bz0 = bias[c0];
    const float bz1 = bias[c1];
    __syncthreads();

    const float* z00p = zx + (long)b0 * G + c0;
    const float* z01p = z00p + G;
    const float* z10p = zx + (long)b0 * G + c1;
    const float* z11p = z10p + G;

    float c_a = 0.f;
    float c_b = 0.f;
    float zA0[4];
    float zA1[4];
    float zB0[4];
    float zB1[4];
#pragma unroll
    for (int p = 0; p < PF; p++) {
        zA0[p] = z00p[(long)p * ZSTRIDE];
        zA1[p] = z01p[(long)p * ZSTRIDE];
        zB0[p] = z10p[(long)p * ZSTRIDE];
        zB1[p] = z11p[(long)p * ZSTRIDE];
    }

    int cur = 0;
#pragma unroll 4
    for (int t = 0; t < TT; t++) {
        const int s = t & (PF - 1);
        float a00 = zA0[s] + bz0;
        float a01 = zA1[s] + bz0;
        float a10 = zB0[s] + bz1;
        float a11 = zB1[s] + bz1;
        if (t + PF < TT) {
            zA0[s] = z00p[(long)(t + PF) * ZSTRIDE];
            zA1[s] = z01p[(long)(t + PF) * ZSTRIDE];
            zB0[s] = z10p[(long)(t + PF) * ZSTRIDE];
            zB1[s] = z11p[(long)(t + PF) * ZSTRIDE];
        }

#pragma unroll
        for (int kb = 0; kb < 4; kb++) {
            half2 s00 = __floats2half2_rn(0.f, 0.f);
            half2 s01 = __floats2half2_rn(0.f, 0.f);
            half2 s10 = __floats2half2_rn(0.f, 0.f);
            half2 s11 = __floats2half2_rn(0.f, 0.f);
#pragma unroll
            for (int k8 = 0; k8 < 4; k8++) {
                const int kbase = kb * 32 + k8 * 8;
                uint4 hv0 = *reinterpret_cast<const uint4*>(&h_s[cur][0][kbase]);
                uint4 hv1 = *reinterpret_cast<const uint4*>(&h_s[cur][1][kbase]);
                const half2* hp0 = reinterpret_cast<const half2*>(&hv0);
                const half2* hp1 = reinterpret_cast<const half2*>(&hv1);
#pragma unroll
                for (int q = 0; q < 4; q++) {
                    const int k2 = kbase / 2 + q;
                    s00 = __hfma2(w0[k2], hp0[q], s00);
                    s01 = __hfma2(w0[k2], hp1[q], s01);
                    s10 = __hfma2(w1[k2], hp0[q], s10);
                    s11 = __hfma2(w1[k2], hp1[q], s11);
                }
            }
            float2 fa = __half22float2(s00);
            float2 fb = __half22float2(s01);
            float2 fc = __half22float2(s10);
            float2 fd = __half22float2(s11);
            a00 += fa.x + fa.y;
            a01 += fb.x + fb.y;
            a10 += fc.x + fc.y;
            a11 += fd.x + fd.y;
        }

        float mineA  = myrow ? a01 : a00;
        float otherA = myrow ? a00 : a01;
        float mineB  = myrow ? a11 : a10;
        float otherB = myrow ? a10 : a11;
        float p1A = __shfl_xor_sync(0xffffffffu, mineA,  1);
        float rvA = __shfl_xor_sync(0xffffffffu, otherA, 2);
        float p2A = __shfl_xor_sync(0xffffffffu, otherA, 3);
        float p1B = __shfl_xor_sync(0xffffffffu, mineB,  1);
        float rvB = __shfl_xor_sync(0xffffffffu, otherB, 2);
        float p2B = __shfl_xor_sync(0xffffffffu, otherB, 3);

        float zi, zf, zg_, zoo;
        quad_select(g, mineA, p1A, rvA, p2A, zi, zf, zg_, zoo);
        float ig = sigf(zi);
        float fg = sigf(zf);
        float og = sigf(zoo);
        c_a = fg * c_a + ig * fmaxf(zg_, 0.f);
        float hA = og * fmaxf(c_a, 0.f);

        quad_select(g, mineB, p1B, rvB, p2B, zi, zf, zg_, zoo);
        ig = sigf(zi);
        fg = sigf(zf);
        og = sigf(zoo);
        c_b = fg * c_b + ig * fmaxf(zg_, 0.f);
        float hB = og * fmaxf(c_b, 0.f);

        if ((g & 1) == 0) {
            __half hAh = __float2half_rn(hA);
            __half hBh = __float2half_rn(hB);
            h_s[cur ^ 1][myrow][j0]      = hAh;
            h_s[cur ^ 1][myrow][j0 + 64] = hBh;
            long o = ((long)t * BB + b0 + myrow) * U;
            hhi[o + j0]      = hAh;
            hhi[o + j0 + 64] = hBh;
            hlo[o + j0]      = __float2half_rn(hA - __half2float(hAh));
            hlo[o + j0 + 64] = __float2half_rn(hB - __half2float(hBh));
        }
        __syncthreads();
        cur ^= 1;
    }
}

// ---------------- dense head ----------------
__global__ __launch_bounds__(256) void dense_kernel(
    const float* __restrict__ h3, const float* __restrict__ Wd1,
    const float* __restrict__ bd1, const float* __restrict__ Wd2,
    const float* __restrict__ bd2, float* __restrict__ out)
{
    __shared__ float w1[64 * 32];
    __shared__ float w2[32];
    __shared__ float b1s[32];
    const int tid = threadIdx.x;
    for (int i = tid; i < 64 * 32; i += 256) {
        w1[i] = Wd1[i];
    }
    if (tid < 32) {
        w2[tid] = Wd2[tid];
        b1s[tid] = bd1[tid];
    }
    __syncthreads();

    float hr[64];
#pragma unroll
    for (int k4 = 0; k4 < 16; k4++) {
        *reinterpret_cast<float4*>(&hr[4 * k4]) =
            *reinterpret_cast<const float4*>(&h3[tid * 64 + 4 * k4]);
    }

    float o = bd2[0];
#pragma unroll 4
    for (int jj = 0; jj < 32; jj++) {
        float d = b1s[jj];
#pragma unroll
        for (int k = 0; k < 64; k++) {
            d += hr[k] * w1[k * 32 + jj];
        }
        o += fmaxf(d, 0.f) * w2[jj];
    }
    out[tid] = o;
}

// ---------------- launcher ----------------
extern "C" void kernel_launch(void* const* d_in, const int* in_sizes, int n_in,
                              void* d_out, int out_size)
{
    const float* x   = (const float*)d_in[0];
    const float* W1  = (const float*)d_in[1];
    const float* Uw1 = (const float*)d_in[2];
    const float* b1  = (const float*)d_in[3];
    const float* W2  = (const float*)d_in[4];
    const float* Uw2 = (const float*)d_in[5];
    const float* b2  = (const float*)d_in[6];
    const float* W3  = (const float*)d_in[7];
    const float* Uw3 = (const float*)d_in[8];
    const float* b3  = (const float*)d_in[9];
    const float* Wd1 = (const float*)d_in[10];
    const float* bd1 = (const float*)d_in[11];
    const float* Wd2 = (const float*)d_in[12];
    const float* bd2 = (const float*)d_in[13];

    float* zx1;
    float* zx2;
    float* zx3;
    float* h3;
    __half* xhi;
    __half* xlo;
    __half* h1hi;
    __half* h1lo;
    __half* h2hi;
    __half* h2lo;
    __half* w1hi;
    __half* w1lo;
    __half* w2hi;
    __half* w2lo;
    __half* w3hi;
    __half* w3lo;
    cudaGetSymbolAddress((void**)&zx1,  g_zx1);
    cudaGetSymbolAddress((void**)&zx2,  g_zx2);
    cudaGetSymbolAddress((void**)&zx3,  g_zx3);
    cudaGetSymbolAddress((void**)&h3,   g_h3);
    cudaGetSymbolAddress((void**)&xhi,  g_xhi);
    cudaGetSymbolAddress((void**)&xlo,  g_xlo);
    cudaGetSymbolAddress((void**)&h1hi, g_h1hi);
    cudaGetSymbolAddress((void**)&h1lo, g_h1lo);
    cudaGetSymbolAddress((void**)&h2hi, g_h2hi);
    cudaGetSymbolAddress((void**)&h2lo, g_h2lo);
    cudaGetSymbolAddress((void**)&w1hi, g_w1hi);
    cudaGetSymbolAddress((void**)&w1lo, g_w1lo);
    cudaGetSymbolAddress((void**)&w2hi, g_w2hi);
    cudaGetSymbolAddress((void**)&w2lo, g_w2lo);
    cudaGetSymbolAddress((void**)&w3hi, g_w3hi);
    cudaGetSymbolAddress((void**)&w3lo, g_w3lo);

    // pre-split inputs and weights
    split_kernel<<<1024, 256>>>(x,  xhi,  xlo,  BB * TT * 64);
    split_kernel<<<64,   256>>>(W1, w1hi, w1lo, 64 * 512);
    split_kernel<<<64,   256>>>(W2, w2hi, w2lo, 128 * 256);
    split_kernel<<<64,   256>>>(W3, w3hi, w3lo, 64 * 256);

    proj_gemm_tc<64, 512, true ><<<dim3(1024, 4), 256>>>(xhi, xlo, w1hi, w1lo, zx1);
    lstm1_rec<<<128, 256>>>(zx1, Uw1, b1, h1hi, h1lo);

    proj_gemm_tc<128, 256, false><<<dim3(1024, 2), 256>>>(h1hi, h1lo, w2hi, w2lo, zx2);
    lstm64_rec<true ><<<256, 128>>>(zx2, Uw2, b2, h2hi, h2lo, (float*)0);

    proj_gemm_tc<64, 256, false><<<dim3(1024, 2), 256>>>(h2hi, h2lo, w3hi, w3lo, zx3);
    lstm64_rec<false><<<256, 128>>>(zx3, Uw3, b3, (__half*)0, (__half*)0, h3);

    dense_kernel<<<1, 256>>>(h3, Wd1, bd1, Wd2, bd2, (float*)d_out);
}